// round 2
// baseline (speedup 1.0000x reference)
#include <cuda_runtime.h>
#include <math.h>

// Problem constants (fixed by the reference).
#define NN   500000
#define HID  256
#define NC   104
#define NG   2048
#define DIN  106     // NC + AUX
#define GX   128
#define AUXD 2

// Scratch: per-graph pooled readout (fp32 accumulators).
__device__ float g_readout[NG * NC];

// ---------------------------------------------------------------------------
// Kernel 1: zero the readout accumulator.
// ---------------------------------------------------------------------------
__global__ void zero_readout_kernel() {
    int i = blockIdx.x * blockDim.x + threadIdx.x;
    if (i < NG * NC) g_readout[i] = 0.0f;
}

// ---------------------------------------------------------------------------
// Kernel 2: fused node GEMMs + gate + atomic segment scatter.
//   gate_logit[n,c] = concat(Xi,Xf)[n,:] @ Wg[:,c]         (K = 512)
//   trans[n,c]      = Xf[n,:] @ Wt[:,c]                    (K = 256)
//   nodewise[n,c]   = sigmoid(gate_logit + bg) * (trans + bt)
//   g_readout[gid[n], c] += nodewise[n,c]
//
// Tiling: BM=128 nodes x BN=128 classes (104 padded to 128), BK=16.
// 256 threads, 8x8 micro-tile per thread.
// ---------------------------------------------------------------------------
#define BM 128
#define BK 16
#define SXS 132          // padded stride for transposed X staging

__global__ __launch_bounds__(256, 1)
void node_gemm_scatter_kernel(const float* __restrict__ Xi,
                              const float* __restrict__ Xf,
                              const int*   __restrict__ gid,
                              const float* __restrict__ Wg,
                              const float* __restrict__ bgv,
                              const float* __restrict__ Wt,
                              const float* __restrict__ btv) {
    __shared__ float s_x[BK * SXS];     // [k][m], transposed
    __shared__ float s_wg[BK * 128];    // [k][c], padded classes
    __shared__ float s_wt[BK * 128];

    const int tid = threadIdx.x;
    const int tx  = tid & 15;    // class-group: classes tx*8 .. tx*8+7
    const int ty  = tid >> 4;    // node-group:  nodes  ty*8 .. ty*8+7
    const int m0  = blockIdx.x * BM;

    float accg[8][8];
    float acct[8][8];
#pragma unroll
    for (int i = 0; i < 8; i++)
#pragma unroll
        for (int j = 0; j < 8; j++) { accg[i][j] = 0.0f; acct[i][j] = 0.0f; }

    for (int k0 = 0; k0 < 2 * HID; k0 += BK) {
        const bool second = (k0 >= HID);
        const float* X = second ? Xf : Xi;
        const int kcol  = second ? (k0 - HID) : k0;

        // ---- stage X tile (transposed into s_x[k][m]) ----
        {
            // 128 rows x 4 float4-groups = 512 float4 slots; 2 per thread.
#pragma unroll
            for (int i = 0; i < 2; i++) {
                int s  = tid * 2 + i;
                int r  = s >> 2;          // node row within tile
                int cg = s & 3;           // k-group of 4
                int node = m0 + r;
                float4 v = make_float4(0.f, 0.f, 0.f, 0.f);
                if (node < NN)
                    v = *(const float4*)(X + (size_t)node * HID + kcol + cg * 4);
                s_x[(cg * 4 + 0) * SXS + r] = v.x;
                s_x[(cg * 4 + 1) * SXS + r] = v.y;
                s_x[(cg * 4 + 2) * SXS + r] = v.z;
                s_x[(cg * 4 + 3) * SXS + r] = v.w;
            }
        }
        // ---- stage weight tiles (zero-pad classes 104..127) ----
        {
            int r  = tid >> 4;           // k row within tile (0..15)
            int c0 = (tid & 15) * 8;
#pragma unroll
            for (int j = 0; j < 8; j++) {
                int c = c0 + j;
                float wg = (c < NC) ? Wg[(size_t)(k0 + r) * NC + c] : 0.0f;
                s_wg[r * 128 + c] = wg;
                if (second) {
                    float wt = (c < NC) ? Wt[(size_t)(kcol + r) * NC + c] : 0.0f;
                    s_wt[r * 128 + c] = wt;
                }
            }
        }
        __syncthreads();

        if (!second) {
#pragma unroll 4
            for (int kk = 0; kk < BK; kk++) {
                float4 xa = *(const float4*)&s_x[kk * SXS + ty * 8];
                float4 xb = *(const float4*)&s_x[kk * SXS + ty * 8 + 4];
                float4 wa = *(const float4*)&s_wg[kk * 128 + tx * 8];
                float4 wb = *(const float4*)&s_wg[kk * 128 + tx * 8 + 4];
                float xm[8] = {xa.x, xa.y, xa.z, xa.w, xb.x, xb.y, xb.z, xb.w};
                float wn[8] = {wa.x, wa.y, wa.z, wa.w, wb.x, wb.y, wb.z, wb.w};
#pragma unroll
                for (int i = 0; i < 8; i++)
#pragma unroll
                    for (int j = 0; j < 8; j++)
                        accg[i][j] = fmaf(xm[i], wn[j], accg[i][j]);
            }
        } else {
#pragma unroll 4
            for (int kk = 0; kk < BK; kk++) {
                float4 xa = *(const float4*)&s_x[kk * SXS + ty * 8];
                float4 xb = *(const float4*)&s_x[kk * SXS + ty * 8 + 4];
                float4 ga = *(const float4*)&s_wg[kk * 128 + tx * 8];
                float4 gb = *(const float4*)&s_wg[kk * 128 + tx * 8 + 4];
                float4 ta = *(const float4*)&s_wt[kk * 128 + tx * 8];
                float4 tb = *(const float4*)&s_wt[kk * 128 + tx * 8 + 4];
                float xm[8] = {xa.x, xa.y, xa.z, xa.w, xb.x, xb.y, xb.z, xb.w};
                float gn[8] = {ga.x, ga.y, ga.z, ga.w, gb.x, gb.y, gb.z, gb.w};
                float tn[8] = {ta.x, ta.y, ta.z, ta.w, tb.x, tb.y, tb.z, tb.w};
#pragma unroll
                for (int i = 0; i < 8; i++)
#pragma unroll
                    for (int j = 0; j < 8; j++) {
                        accg[i][j] = fmaf(xm[i], gn[j], accg[i][j]);
                        acct[i][j] = fmaf(xm[i], tn[j], acct[i][j]);
                    }
            }
        }
        __syncthreads();
    }

    // ---- epilogue: sigmoid gate, multiply, atomic scatter ----
#pragma unroll
    for (int i = 0; i < 8; i++) {
        int node = m0 + ty * 8 + i;
        if (node >= NN) continue;
        int g = gid[node];
        float* dst = g_readout + (size_t)g * NC;
#pragma unroll
        for (int j = 0; j < 8; j++) {
            int c = tx * 8 + j;
            if (c < NC) {
                float gl   = accg[i][j] + bgv[c];
                float gate = 1.0f / (1.0f + __expf(-gl));
                float val  = gate * (acct[i][j] + btv[c]);
                atomicAdd(dst + c, val);
            }
        }
    }
}

// ---------------------------------------------------------------------------
// Kernel 3: per-graph BatchNorm (eval) + MLP (106 -> 128 -> 104).
// One block (128 threads) per graph.
// ---------------------------------------------------------------------------
__global__ __launch_bounds__(GX)
void graph_mlp_kernel(const float* __restrict__ aux,
                      const float* __restrict__ bn_g,
                      const float* __restrict__ bn_b,
                      const float* __restrict__ bn_m,
                      const float* __restrict__ bn_v,
                      const float* __restrict__ W1,
                      const float* __restrict__ b1,
                      const float* __restrict__ W2,
                      const float* __restrict__ b2,
                      float* __restrict__ out) {
    __shared__ float s_norm[DIN];
    __shared__ float s_h[GX];
    int g = blockIdx.x;
    int t = threadIdx.x;

    if (t < DIN) {
        float e = (t < NC) ? g_readout[(size_t)g * NC + t]
                           : aux[(size_t)g * AUXD + (t - NC)];
        s_norm[t] = (e - bn_m[t]) * rsqrtf(bn_v[t] + 1e-5f) * bn_g[t] + bn_b[t];
    }
    __syncthreads();

    float h = b1[t];
#pragma unroll 2
    for (int k = 0; k < DIN; k++)
        h = fmaf(s_norm[k], W1[k * GX + t], h);
    s_h[t] = fmaxf(h, 0.0f);
    __syncthreads();

    if (t < NC) {
        float o = b2[t];
#pragma unroll 2
        for (int k = 0; k < GX; k++)
            o = fmaf(s_h[k], W2[k * NC + t], o);
        out[(size_t)g * NC + t] = o;
    }
}

// ---------------------------------------------------------------------------
// Launch
// ---------------------------------------------------------------------------
extern "C" void kernel_launch(void* const* d_in, const int* in_sizes, int n_in,
                              void* d_out, int out_size) {
    const float* Xi  = (const float*)d_in[0];
    const float* Xf  = (const float*)d_in[1];
    const float* aux = (const float*)d_in[2];
    const int*   gid = (const int*)d_in[3];
    // Hedge on whether the scalar num_graphs occupies a slot.
    int w = (n_in >= 17 && in_sizes[4] <= 1) ? 5 : 4;
    const float* Wg   = (const float*)d_in[w + 0];
    const float* bg   = (const float*)d_in[w + 1];
    const float* Wt   = (const float*)d_in[w + 2];
    const float* bt   = (const float*)d_in[w + 3];
    const float* bn_g = (const float*)d_in[w + 4];
    const float* bn_b = (const float*)d_in[w + 5];
    const float* bn_m = (const float*)d_in[w + 6];
    const float* bn_v = (const float*)d_in[w + 7];
    const float* W1   = (const float*)d_in[w + 8];
    const float* b1   = (const float*)d_in[w + 9];
    const float* W2   = (const float*)d_in[w + 10];
    const float* b2   = (const float*)d_in[w + 11];
    float* out = (float*)d_out;

    zero_readout_kernel<<<(NG * NC + 255) / 256, 256>>>();
    node_gemm_scatter_kernel<<<(NN + BM - 1) / BM, 256>>>(Xi, Xf, gid, Wg, bg, Wt, bt);
    graph_mlp_kernel<<<NG, GX>>>(aux, bn_g, bn_b, bn_m, bn_v, W1, b1, W2, b2, out);
}

// round 5
// speedup vs baseline: 3.0657x; 3.0657x over previous
#include <cuda_runtime.h>
#include <math.h>
#include <stdint.h>

// Problem constants (fixed by the reference).
#define NN   500000
#define HID  256
#define NC   104
#define NG   2048
#define DIN  106
#define GX   128
#define AUXD 2

// Scratch: per-graph pooled readout (fp32 accumulators).
__device__ float g_readout[NG * NC];

// ---------------------------------------------------------------------------
// Tiling constants
// ---------------------------------------------------------------------------
#define BM 128
#define SAS 40                  // A row stride (floats), 32 + pad
#define SWS 40                  // weight row stride (floats)
#define A_FLOATS (128 * SAS)    // 5120
#define W_FLOATS (128 * SWS)    // 5120
#define BUF_FLOATS (A_FLOATS + 2 * W_FLOATS)   // 15360
#define SMEM_TOTAL (2 * BUF_FLOATS * 4)        // 122880 bytes
#define NCHUNK 16

// ---------------------------------------------------------------------------
// Kernel 1: zero the readout accumulator.
// ---------------------------------------------------------------------------
__global__ void zero_readout_kernel() {
    int i = blockIdx.x * blockDim.x + threadIdx.x;
    if (i < NG * NC) g_readout[i] = 0.0f;
}

// ---------------------------------------------------------------------------
// tf32 warp MMA (m16n8k8). fp32 register bits are used as tf32 operands.
// ---------------------------------------------------------------------------
__device__ __forceinline__ void mma8(float* c, const uint32_t* a,
                                     uint32_t b0, uint32_t b1) {
    asm volatile(
        "mma.sync.aligned.m16n8k8.row.col.f32.tf32.tf32.f32 "
        "{%0,%1,%2,%3}, {%4,%5,%6,%7}, {%8,%9}, {%0,%1,%2,%3};"
        : "+f"(c[0]), "+f"(c[1]), "+f"(c[2]), "+f"(c[3])
        : "r"(a[0]), "r"(a[1]), "r"(a[2]), "r"(a[3]), "r"(b0), "r"(b1));
}

// ---------------------------------------------------------------------------
// Staging helpers (K-permuted so fragments are contiguous float2s).
// perm within each 8-k block: k' = (k&3)*2 + ((k>>2)&1)
// ---------------------------------------------------------------------------
__device__ __forceinline__ void loadA(const float* __restrict__ X, long m0,
                                      int kcol, int tid, float4* r) {
#pragma unroll
    for (int u = 0; u < 4; u++) {
        int s = tid + u * 256;           // 0..1023
        int row = s >> 3, q = s & 7;
        long node = m0 + row;
        r[u] = (node < NN) ? *(const float4*)(X + node * HID + kcol + q * 4)
                           : make_float4(0.f, 0.f, 0.f, 0.f);
    }
}
__device__ __forceinline__ void stsA(float* buf, int tid, const float4* r) {
#pragma unroll
    for (int u = 0; u < 4; u++) {
        int s = tid + u * 256;
        int row = s >> 3, q = s & 7;
        float* dst = buf + row * SAS + (q >> 1) * 8 + (q & 1);
        const float* v = &r[u].x;
#pragma unroll
        for (int i = 0; i < 4; i++) dst[i * 2] = v[i];
    }
}
__device__ __forceinline__ void loadW(const float* __restrict__ W, int kbase,
                                      int tid, float4* r) {
#pragma unroll
    for (int u = 0; u < 4; u++) {
        int s = tid + u * 256;
        if (s < 832) {                   // 32 k * 26 c-quads (104 = 26*4)
            int k = s & 31, cg = s >> 5;
            r[u] = *(const float4*)(W + (long)(kbase + k) * NC + cg * 4);
        }
    }
}
__device__ __forceinline__ void stsW(float* buf, int tid, const float4* r) {
#pragma unroll
    for (int u = 0; u < 4; u++) {
        int s = tid + u * 256;
        if (s < 832) {
            int k = s & 31, cg = s >> 5;
            int kp = (k >> 3) * 8 + (k & 3) * 2 + ((k >> 2) & 1);
            float* dst = buf + cg * 4 * SWS + kp;
            const float* v = &r[u].x;
#pragma unroll
            for (int i = 0; i < 4; i++) dst[i * SWS] = v[i];
        }
    }
}

// ---------------------------------------------------------------------------
// Kernel 2: tf32 mma.sync node GEMMs + gate + segment scatter.
// 8 warps = 4(M) x 2(N); warp tile 32 x 64.
// ---------------------------------------------------------------------------
__global__ void __launch_bounds__(256, 1)
node_gemm_mma_kernel(const float* __restrict__ Xi,
                     const float* __restrict__ Xf,
                     const int*   __restrict__ gid,
                     const float* __restrict__ Wg,
                     const float* __restrict__ bgv,
                     const float* __restrict__ Wt,
                     const float* __restrict__ btv) {
    extern __shared__ float smem[];
    const int tid  = threadIdx.x;
    const int wid  = tid >> 5, lane = tid & 31;
    const int g4   = lane >> 2, tig = lane & 3;
    const int wm   = wid & 3,  wn  = wid >> 2;
    const long m0  = (long)blockIdx.x * BM;

    float accg[2][8][4];
    float acct[2][8][4];
#pragma unroll
    for (int mf = 0; mf < 2; mf++)
#pragma unroll
        for (int nf = 0; nf < 8; nf++)
#pragma unroll
            for (int k = 0; k < 4; k++) { accg[mf][nf][k] = 0.f; acct[mf][nf][k] = 0.f; }

    float4 ra[4], rg[4], rt[4];

    // prologue: stage chunk 0
    loadA(Xi, m0, 0, tid, ra);
    loadW(Wg, 0, tid, rg);
    stsA(smem, tid, ra);
    stsW(smem + A_FLOATS, tid, rg);
    __syncthreads();

    for (int i = 0; i < NCHUNK; i++) {
        const int   cur  = i & 1;
        const int   nxt  = cur ^ 1;
        const bool  second  = (i >= 8);
        const bool  nsecond = (i + 1 >= 8);
        float* bufc = smem + cur * BUF_FLOATS;
        float* bufn = smem + nxt * BUF_FLOATS;

        // prefetch next chunk into registers (overlaps with MMA below)
        if (i < NCHUNK - 1) {
            const float* Xn = nsecond ? Xf : Xi;
            loadA(Xn, m0, ((i + 1) & 7) * 32, tid, ra);
            loadW(Wg, (i + 1) * 32, tid, rg);
            if (nsecond) loadW(Wt, (i + 1 - 8) * 32, tid, rt);
        }

        // compute current chunk
        {
            float* sA = bufc;
            float* sG = bufc + A_FLOATS;
            float* sT = bufc + A_FLOATS + W_FLOATS;
#pragma unroll
            for (int blk = 0; blk < 4; blk++) {
                uint32_t a[2][4];
#pragma unroll
                for (int mf = 0; mf < 2; mf++) {
                    int row = wm * 32 + mf * 16 + g4;
                    float2 lo = *(float2*)(sA + row * SAS + blk * 8 + tig * 2);
                    float2 hi = *(float2*)(sA + (row + 8) * SAS + blk * 8 + tig * 2);
                    a[mf][0] = __float_as_uint(lo.x);
                    a[mf][1] = __float_as_uint(hi.x);
                    a[mf][2] = __float_as_uint(lo.y);
                    a[mf][3] = __float_as_uint(hi.y);
                }
#pragma unroll
                for (int nf = 0; nf < 8; nf++) {
                    int col = wn * 64 + nf * 8 + g4;
                    float2 bf = *(float2*)(sG + col * SWS + blk * 8 + tig * 2);
                    uint32_t b0 = __float_as_uint(bf.x), b1 = __float_as_uint(bf.y);
                    mma8(accg[0][nf], a[0], b0, b1);
                    mma8(accg[1][nf], a[1], b0, b1);
                    if (second) {
                        float2 tf = *(float2*)(sT + col * SWS + blk * 8 + tig * 2);
                        uint32_t t0 = __float_as_uint(tf.x), t1 = __float_as_uint(tf.y);
                        mma8(acct[0][nf], a[0], t0, t1);
                        mma8(acct[1][nf], a[1], t0, t1);
                    }
                }
            }
        }

        // drain prefetch registers into the other buffer
        if (i < NCHUNK - 1) {
            stsA(bufn, tid, ra);
            stsW(bufn + A_FLOATS, tid, rg);
            if (nsecond) stsW(bufn + A_FLOATS + W_FLOATS, tid, rt);
        }
        __syncthreads();
    }

    // ---- epilogue: bias + sigmoid gate, then segment scatter ----
    float bgr[8][2], btr[8][2];
#pragma unroll
    for (int nf = 0; nf < 8; nf++)
#pragma unroll
        for (int j = 0; j < 2; j++) {
            int c = wn * 64 + nf * 8 + tig * 2 + j;
            bgr[nf][j] = (c < NC) ? __ldg(bgv + c) : 0.f;
            btr[nf][j] = (c < NC) ? __ldg(btv + c) : 0.f;
        }

    // fuse gate into accg in place (registers reused)
#pragma unroll
    for (int mf = 0; mf < 2; mf++)
#pragma unroll
        for (int nf = 0; nf < 8; nf++)
#pragma unroll
            for (int rsel = 0; rsel < 2; rsel++)
#pragma unroll
                for (int j = 0; j < 2; j++) {
                    int idx = rsel * 2 + j;
                    float gl = accg[mf][nf][idx] + bgr[nf][j];
                    float gate = 1.0f / (1.0f + __expf(-gl));
                    accg[mf][nf][idx] = gate * (acct[mf][nf][idx] + btr[nf][j]);
                }

    const long nb = m0 + wm * 32;
    const bool tail = (nb + 31 >= NN);
    int gf = -1, gl2 = -2;
    if (!tail) {
        if (lane == 0) { gf = gid[nb]; gl2 = gid[nb + 31]; }
        gf  = __shfl_sync(0xffffffffu, gf, 0);
        gl2 = __shfl_sync(0xffffffffu, gl2, 0);
    }

    if (!tail && gf == gl2) {
        // warp spans one graph (sorted segment): reduce 32 rows per column.
        float* dst = g_readout + (size_t)gf * NC;
#pragma unroll
        for (int nf = 0; nf < 8; nf++)
#pragma unroll
            for (int j = 0; j < 2; j++) {
                float s = accg[0][nf][j] + accg[0][nf][2 + j] +
                          accg[1][nf][j] + accg[1][nf][2 + j];
                s += __shfl_xor_sync(0xffffffffu, s, 4);
                s += __shfl_xor_sync(0xffffffffu, s, 8);
                s += __shfl_xor_sync(0xffffffffu, s, 16);
                if (g4 == 0) {
                    int c = wn * 64 + nf * 8 + tig * 2 + j;
                    if (c < NC) atomicAdd(dst + c, s);
                }
            }
    } else {
#pragma unroll
        for (int mf = 0; mf < 2; mf++)
#pragma unroll
            for (int rsel = 0; rsel < 2; rsel++) {
                long node = nb + mf * 16 + rsel * 8 + g4;
                if (node < NN) {
                    float* dst = g_readout + (size_t)gid[node] * NC;
#pragma unroll
                    for (int nf = 0; nf < 8; nf++)
#pragma unroll
                        for (int j = 0; j < 2; j++) {
                            int c = wn * 64 + nf * 8 + tig * 2 + j;
                            if (c < NC) atomicAdd(dst + c, accg[mf][nf][rsel * 2 + j]);
                        }
                }
            }
    }
}

// ---------------------------------------------------------------------------
// Kernel 3: per-graph BatchNorm (eval) + MLP (106 -> 128 -> 104).
// ---------------------------------------------------------------------------
__global__ __launch_bounds__(GX)
void graph_mlp_kernel(const float* __restrict__ aux,
                      const float* __restrict__ bn_g,
                      const float* __restrict__ bn_b,
                      const float* __restrict__ bn_m,
                      const float* __restrict__ bn_v,
                      const float* __restrict__ W1,
                      const float* __restrict__ b1,
                      const float* __restrict__ W2,
                      const float* __restrict__ b2,
                      float* __restrict__ out) {
    __shared__ float s_norm[DIN];
    __shared__ float s_h[GX];
    int g = blockIdx.x;
    int t = threadIdx.x;

    if (t < DIN) {
        float e = (t < NC) ? g_readout[(size_t)g * NC + t]
                           : aux[(size_t)g * AUXD + (t - NC)];
        s_norm[t] = (e - bn_m[t]) * rsqrtf(bn_v[t] + 1e-5f) * bn_g[t] + bn_b[t];
    }
    __syncthreads();

    float h = b1[t];
#pragma unroll 2
    for (int k = 0; k < DIN; k++)
        h = fmaf(s_norm[k], W1[k * GX + t], h);
    s_h[t] = fmaxf(h, 0.0f);
    __syncthreads();

    if (t < NC) {
        float o = b2[t];
#pragma unroll 2
        for (int k = 0; k < GX; k++)
            o = fmaf(s_h[k], W2[k * NC + t], o);
        out[(size_t)g * NC + t] = o;
    }
}

// ---------------------------------------------------------------------------
// Launch
// ---------------------------------------------------------------------------
extern "C" void kernel_launch(void* const* d_in, const int* in_sizes, int n_in,
                              void* d_out, int out_size) {
    const float* Xi  = (const float*)d_in[0];
    const float* Xf  = (const float*)d_in[1];
    const float* aux = (const float*)d_in[2];
    const int*   gid = (const int*)d_in[3];
    int w = (n_in >= 17 && in_sizes[4] <= 1) ? 5 : 4;
    const float* Wg   = (const float*)d_in[w + 0];
    const float* bg   = (const float*)d_in[w + 1];
    const float* Wt   = (const float*)d_in[w + 2];
    const float* bt   = (const float*)d_in[w + 3];
    const float* bn_g = (const float*)d_in[w + 4];
    const float* bn_b = (const float*)d_in[w + 5];
    const float* bn_m = (const float*)d_in[w + 6];
    const float* bn_v = (const float*)d_in[w + 7];
    const float* W1   = (const float*)d_in[w + 8];
    const float* b1   = (const float*)d_in[w + 9];
    const float* W2   = (const float*)d_in[w + 10];
    const float* b2   = (const float*)d_in[w + 11];
    float* out = (float*)d_out;

    cudaFuncSetAttribute(node_gemm_mma_kernel,
                         cudaFuncAttributeMaxDynamicSharedMemorySize, SMEM_TOTAL);

    zero_readout_kernel<<<(NG * NC + 255) / 256, 256>>>();
    node_gemm_mma_kernel<<<(NN + BM - 1) / BM, 256, SMEM_TOTAL>>>(
        Xi, Xf, gid, Wg, bg, Wt, bt);
    graph_mlp_kernel<<<NG, GX>>>(aux, bn_g, bn_b, bn_m, bn_v, W1, b1, W2, b2, out);
}